// round 12
// baseline (speedup 1.0000x reference)
#include <cuda_runtime.h>
#include <cuda_bf16.h>
#include <math.h>
#include <stdint.h>

#define SQ   2048
#define DIM  4096
#define NH   32
#define NKVH 8
#define HD   128
#define KVD  (NKVH*HD)   // 1024
#define KTOT 4096

// ---------------- scratch ----------------
__device__ __align__(16) __nv_bfloat16 g_xhi[(size_t)SQ * DIM];
__device__ __align__(16) __nv_bfloat16 g_xlo[(size_t)SQ * DIM];
__device__ __align__(16) __nv_bfloat16 g_atthi[(size_t)SQ * DIM];
__device__ __align__(16) __nv_bfloat16 g_attlo[(size_t)SQ * DIM];
__device__ __align__(16) __nv_bfloat16 g_qhi[(size_t)SQ * DIM];
__device__ __align__(16) __nv_bfloat16 g_qlo[(size_t)SQ * DIM];
__device__ __align__(16) __nv_bfloat16 g_khi[(size_t)SQ * KVD];
__device__ __align__(16) __nv_bfloat16 g_klo[(size_t)SQ * KVD];
__device__ __align__(16) __nv_bfloat16 g_vhi[(size_t)SQ * KVD];
__device__ __align__(16) __nv_bfloat16 g_vlo[(size_t)SQ * KVD];
__device__ __align__(16) __nv_bfloat16 g_wqT_hi[(size_t)DIM * DIM];
__device__ __align__(16) __nv_bfloat16 g_wqT_lo[(size_t)DIM * DIM];
__device__ __align__(16) __nv_bfloat16 g_wkT_hi[(size_t)KVD * DIM];
__device__ __align__(16) __nv_bfloat16 g_wkT_lo[(size_t)KVD * DIM];
__device__ __align__(16) __nv_bfloat16 g_wvT_hi[(size_t)KVD * DIM];
__device__ __align__(16) __nv_bfloat16 g_wvT_lo[(size_t)KVD * DIM];
__device__ __align__(16) __nv_bfloat16 g_woT_hi[(size_t)DIM * DIM];
__device__ __align__(16) __nv_bfloat16 g_woT_lo[(size_t)DIM * DIM];

__device__ __forceinline__ uint32_t smem_u32(const void* p) {
    return (uint32_t)__cvta_generic_to_shared(p);
}
#define LDSM_X4(r0, r1, r2, r3, addr)                                          \
    asm volatile("ldmatrix.sync.aligned.m8n8.x4.shared.b16 {%0,%1,%2,%3}, [%4];" \
                 : "=r"(r0), "=r"(r1), "=r"(r2), "=r"(r3) : "r"(addr))
#define LDSM_X4_T(r0, r1, r2, r3, addr)                                        \
    asm volatile("ldmatrix.sync.aligned.m8n8.x4.trans.shared.b16 {%0,%1,%2,%3}, [%4];" \
                 : "=r"(r0), "=r"(r1), "=r"(r2), "=r"(r3) : "r"(addr))
#define MMA16816(c, a, b0_, b1_)                                               \
    asm volatile("mma.sync.aligned.m16n8k16.row.col.f32.bf16.bf16.f32 "        \
                 "{%0,%1,%2,%3}, {%4,%5,%6,%7}, {%8,%9}, {%0,%1,%2,%3};"       \
                 : "+f"((c)[0]), "+f"((c)[1]), "+f"((c)[2]), "+f"((c)[3])      \
                 : "r"((a)[0]), "r"((a)[1]), "r"((a)[2]), "r"((a)[3]),         \
                   "r"(b0_), "r"(b1_))
__device__ __forceinline__ void cp16(uint32_t saddr, const void* g) {
    asm volatile("cp.async.cg.shared.global [%0], [%1], 16;"
                 :: "r"(saddr), "l"(g) : "memory");
}
#define CP_COMMIT() asm volatile("cp.async.commit_group;" ::: "memory")
#define CP_WAIT(n)  asm volatile("cp.async.wait_group %0;" :: "n"(n) : "memory")

__device__ __forceinline__ uint32_t pack_bf16x2(float lo, float hi) {
    uint32_t r;
    asm("cvt.rn.bf16x2.f32 %0, %1, %2;" : "=r"(r) : "f"(hi), "f"(lo));
    return r;
}
__device__ __forceinline__ float exp_fast(float x) {
    float t = fmaxf(x * 1.4426950408889634f, -126.0f);
    float fi = floorf(t);
    float f = t - fi;
    float p = fmaf(f, 0.0013333558f, 0.0096181291f);
    p = fmaf(f, p, 0.0555041087f);
    p = fmaf(f, p, 0.2402265069f);
    p = fmaf(f, p, 0.6931471806f);
    p = fmaf(f, p, 1.0f);
    int i = (int)fi;
    return __int_as_float((uint32_t)(i + 127) << 23) * p;
}

// ---------------- conversion kernels ----------------
__global__ __launch_bounds__(256)
void split_rows(const float* __restrict__ X, __nv_bfloat16* __restrict__ hi,
                __nv_bfloat16* __restrict__ lo)
{
    size_t i = (size_t)blockIdx.x * 256 + threadIdx.x;
    float v = X[i];
    __nv_bfloat16 h = __float2bfloat16(v);
    hi[i] = h;
    lo[i] = __float2bfloat16(v - __bfloat162float(h));
}

__global__ __launch_bounds__(256)
void transpose_split(const float* __restrict__ W, __nv_bfloat16* __restrict__ Thi,
                     __nv_bfloat16* __restrict__ Tlo, int K, int N)
{
    __shared__ float tile[32][33];
    int n0 = blockIdx.x * 32, k0 = blockIdx.y * 32;
    int tx = threadIdx.x & 31, ty = threadIdx.x >> 5;
#pragma unroll
    for (int j = 0; j < 4; j++)
        tile[ty + j * 8][tx] = W[(size_t)(k0 + ty + j * 8) * N + n0 + tx];
    __syncthreads();
#pragma unroll
    for (int j = 0; j < 4; j++) {
        float v = tile[tx][ty + j * 8];
        __nv_bfloat16 h = __float2bfloat16(v);
        __nv_bfloat16 l = __float2bfloat16(v - __bfloat162float(h));
        size_t o = (size_t)(n0 + ty + j * 8) * K + k0 + tx;
        Thi[o] = h;
        Tlo[o] = l;
    }
}

// ---------------- QKV mega-GEMM: CTA 128x256, warps 64x64, 3-stage cp.async ----
#define SPITCH 40
#define AOFF_L (128 * SPITCH)
#define BOFF_H (2 * 128 * SPITCH)
#define BOFF_L (2 * 128 * SPITCH + 256 * SPITCH)
#define SLOT_EL (SPITCH * (128 + 128 + 256 + 256))
#define QKV_SMEM (3 * SLOT_EL * 2)

struct QkvOut {
    const __nv_bfloat16 *bh, *bl;
    __nv_bfloat16 *oh, *ol;
    int nloc, ldo, rope;
};

__global__ void __launch_bounds__(256, 1)
gemm_qkv(const __nv_bfloat16* __restrict__ Ahi, const __nv_bfloat16* __restrict__ Alo,
         const __nv_bfloat16* __restrict__ Wqh, const __nv_bfloat16* __restrict__ Wql,
         const __nv_bfloat16* __restrict__ Wkh, const __nv_bfloat16* __restrict__ Wkl,
         const __nv_bfloat16* __restrict__ Wvh, const __nv_bfloat16* __restrict__ Wvl,
         __nv_bfloat16* __restrict__ Qh, __nv_bfloat16* __restrict__ Ql,
         __nv_bfloat16* __restrict__ Kh, __nv_bfloat16* __restrict__ Kl,
         __nv_bfloat16* __restrict__ Vh, __nv_bfloat16* __restrict__ Vl,
         const float* __restrict__ fc, const float* __restrict__ fs)
{
    extern __shared__ __nv_bfloat16 dsm[];
    int tid = threadIdx.x, wid = tid >> 5, lane = tid & 31;
    int m0 = blockIdx.y * 128;
    int xb = blockIdx.x;

    QkvOut oc;
    if (xb < 16)      { oc = {Wqh, Wql, Qh, Ql, xb * 256, DIM, 1}; }
    else if (xb < 20) { oc = {Wkh, Wkl, Kh, Kl, (xb - 16) * 256, KVD, 1}; }
    else              { oc = {Wvh, Wvl, Vh, Vl, (xb - 20) * 256, KVD, 0}; }

    int wm = (wid & 1) * 64, wn = (wid >> 1) * 64;
    uint32_t smbase = smem_u32(dsm);
    int arow = tid >> 1, ahalf = (tid & 1) * 16;

    float acc[4][8][4];
#pragma unroll
    for (int i = 0; i < 4; i++)
#pragma unroll
        for (int j = 0; j < 8; j++)
#pragma unroll
            for (int c = 0; c < 4; c++) acc[i][j][c] = 0.f;

    auto stage = [&](int c, int s) {
        uint32_t sb = smbase + (uint32_t)s * (SLOT_EL * 2);
        size_t gA = (size_t)(m0 + arow) * KTOT + c * 32 + ahalf;
        uint32_t ao = (uint32_t)(arow * SPITCH + ahalf) * 2;
        cp16(sb + ao,                    Ahi + gA);
        cp16(sb + ao + 16,               Ahi + gA + 8);
        cp16(sb + AOFF_L * 2 + ao,       Alo + gA);
        cp16(sb + AOFF_L * 2 + ao + 16,  Alo + gA + 8);
#pragma unroll
        for (int j = 0; j < 2; j++) {
            int brow = arow + j * 128;
            size_t gB = (size_t)(oc.nloc + brow) * KTOT + c * 32 + ahalf;
            uint32_t bo = (uint32_t)(brow * SPITCH + ahalf) * 2;
            cp16(sb + BOFF_H * 2 + bo,      oc.bh + gB);
            cp16(sb + BOFF_H * 2 + bo + 16, oc.bh + gB + 8);
            cp16(sb + BOFF_L * 2 + bo,      oc.bl + gB);
            cp16(sb + BOFF_L * 2 + bo + 16, oc.bl + gB + 8);
        }
    };

    const int NCH = KTOT / 32;  // 128
    stage(0, 0); CP_COMMIT();
    stage(1, 1); CP_COMMIT();

    for (int t = 0; t < NCH; t++) {
        CP_WAIT(1);
        __syncthreads();
        int slot = t % 3;
        uint32_t sb = smbase + (uint32_t)slot * (SLOT_EL * 2);
        uint32_t aH = sb, aL = sb + AOFF_L * 2, bH = sb + BOFF_H * 2, bL = sb + BOFF_L * 2;

#pragma unroll
        for (int ks = 0; ks < 2; ks++) {
            uint32_t bh[8][2], bl[8][2];
#pragma unroll
            for (int jp = 0; jp < 4; jp++) {
                uint32_t off = (uint32_t)((wn + jp * 16 + (lane & 15)) * SPITCH +
                                          ks * 16 + ((lane >> 4) << 3)) * 2;
                uint32_t h0, h1, h2, h3, l0, l1, l2, l3;
                LDSM_X4(h0, h1, h2, h3, bH + off);
                LDSM_X4(l0, l1, l2, l3, bL + off);
                bh[2*jp][0] = h0; bh[2*jp][1] = h2;
                bh[2*jp+1][0] = h1; bh[2*jp+1][1] = h3;
                bl[2*jp][0] = l0; bl[2*jp][1] = l2;
                bl[2*jp+1][0] = l1; bl[2*jp+1][1] = l3;
            }
#pragma unroll
            for (int mi = 0; mi < 4; mi++) {
                uint32_t off = (uint32_t)((wm + mi * 16 + (lane & 15)) * SPITCH +
                                          ks * 16 + ((lane >> 4) << 3)) * 2;
                uint32_t ah[4], al[4];
                LDSM_X4(ah[0], ah[1], ah[2], ah[3], aH + off);
                LDSM_X4(al[0], al[1], al[2], al[3], aL + off);
#pragma unroll
                for (int jn = 0; jn < 8; jn++) {
                    MMA16816(acc[mi][jn], ah, bh[jn][0], bh[jn][1]);
                    MMA16816(acc[mi][jn], ah, bl[jn][0], bl[jn][1]);
                    MMA16816(acc[mi][jn], al, bh[jn][0], bh[jn][1]);
                }
            }
        }
        // 3 slots: staging (t+2)%3 never aliases compute slot t%3 or (t+1)%3 -> no 2nd sync
        if (t + 2 < NCH) { stage(t + 2, (t + 2) % 3); CP_COMMIT(); }
    }

    int qr = lane >> 2, qc = (lane & 3) * 2;
#pragma unroll
    for (int mi = 0; mi < 4; mi++) {
#pragma unroll
        for (int jn = 0; jn < 8; jn++) {
            int r0 = m0 + wm + mi * 16 + qr;
            int cl = oc.nloc + wn + jn * 8 + qc;
            float v00 = acc[mi][jn][0], v01 = acc[mi][jn][1];
            float v10 = acc[mi][jn][2], v11 = acc[mi][jn][3];
            if (oc.rope) {
                int p = (cl & 127) >> 1;
                float c0 = fc[r0 * 64 + p],       s0 = fs[r0 * 64 + p];
                float c1 = fc[(r0 + 8) * 64 + p], s1 = fs[(r0 + 8) * 64 + p];
                float e0 = v00 * c0 - v01 * s0, o0 = v01 * c0 + v00 * s0;
                float e1 = v10 * c1 - v11 * s1, o1 = v11 * c1 + v10 * s1;
                v00 = e0; v01 = o0; v10 = e1; v11 = o1;
            }
            uint32_t hw0 = pack_bf16x2(v00, v01);
            uint32_t lw0 = pack_bf16x2(v00 - __uint_as_float(hw0 << 16),
                                       v01 - __uint_as_float(hw0 & 0xffff0000u));
            uint32_t hw1 = pack_bf16x2(v10, v11);
            uint32_t lw1 = pack_bf16x2(v10 - __uint_as_float(hw1 << 16),
                                       v11 - __uint_as_float(hw1 & 0xffff0000u));
            *(uint32_t*)&oc.oh[(size_t)r0 * oc.ldo + cl]       = hw0;
            *(uint32_t*)&oc.ol[(size_t)r0 * oc.ldo + cl]       = lw0;
            *(uint32_t*)&oc.oh[(size_t)(r0 + 8) * oc.ldo + cl] = hw1;
            *(uint32_t*)&oc.ol[(size_t)(r0 + 8) * oc.ldo + cl] = lw1;
        }
    }
}

// ---------------- O projection ----------------
__global__ void __launch_bounds__(256, 1)
gemm_out(const __nv_bfloat16* __restrict__ Ahi, const __nv_bfloat16* __restrict__ Alo,
         const __nv_bfloat16* __restrict__ Bhi, const __nv_bfloat16* __restrict__ Blo,
         float* __restrict__ C)
{
    extern __shared__ __nv_bfloat16 dsm[];
    int tid = threadIdx.x, wid = tid >> 5, lane = tid & 31;
    int m0 = blockIdx.y * 128, n0 = blockIdx.x * 256;
    int wm = (wid & 1) * 64, wn = (wid >> 1) * 64;
    uint32_t smbase = smem_u32(dsm);
    int arow = tid >> 1, ahalf = (tid & 1) * 16;

    float acc[4][8][4];
#pragma unroll
    for (int i = 0; i < 4; i++)
#pragma unroll
        for (int j = 0; j < 8; j++)
#pragma unroll
            for (int c = 0; c < 4; c++) acc[i][j][c] = 0.f;

    auto stage = [&](int c, int s) {
        uint32_t sb = smbase + (uint32_t)s * (SLOT_EL * 2);
        size_t gA = (size_t)(m0 + arow) * KTOT + c * 32 + ahalf;
        uint32_t ao = (uint32_t)(arow * SPITCH + ahalf) * 2;
        cp16(sb + ao,                   Ahi + gA);
        cp16(sb + ao + 16,              Ahi + gA + 8);
        cp16(sb + AOFF_L * 2 + ao,      Alo + gA);
        cp16(sb + AOFF_L * 2 + ao + 16, Alo + gA + 8);
#pragma unroll
        for (int j = 0; j < 2; j++) {
            int brow = arow + j * 128;
            size_t gB = (size_t)(n0 + brow) * KTOT + c * 32 + ahalf;
            uint32_t bo = (uint32_t)(brow * SPITCH + ahalf) * 2;
            cp16(sb + BOFF_H * 2 + bo,      Bhi + gB);
            cp16(sb + BOFF_H * 2 + bo + 16, Bhi + gB + 8);
            cp16(sb + BOFF_L * 2 + bo,      Blo + gB);
            cp16(sb + BOFF_L * 2 + bo + 16, Blo + gB + 8);
        }
    };

    const int NCH = KTOT / 32;
    stage(0, 0); CP_COMMIT();
    stage(1, 1); CP_COMMIT();

    for (int t = 0; t < NCH; t++) {
        CP_WAIT(1);
        __syncthreads();
        int slot = t % 3;
        uint32_t sb = smbase + (uint32_t)slot * (SLOT_EL * 2);
        uint32_t aH = sb, aL = sb + AOFF_L * 2, bH = sb + BOFF_H * 2, bL = sb + BOFF_L * 2;

#pragma unroll
        for (int ks = 0; ks < 2; ks++) {
            uint32_t bh[8][2], bl[8][2];
#pragma unroll
            for (int jp = 0; jp < 4; jp++) {
                uint32_t off = (uint32_t)((wn + jp * 16 + (lane & 15)) * SPITCH +
                                          ks * 16 + ((lane >> 4) << 3)) * 2;
                uint32_t h0, h1, h2, h3, l0, l1, l2, l3;
                LDSM_X4(h0, h1, h2, h3, bH + off);
                LDSM_X4(l0, l1, l2, l3, bL + off);
                bh[2*jp][0] = h0; bh[2*jp][1] = h2;
                bh[2*jp+1][0] = h1; bh[2*jp+1][1] = h3;
                bl[2*jp][0] = l0; bl[2*jp][1] = l2;
                bl[2*jp+1][0] = l1; bl[2*jp+1][1] = l3;
            }
#pragma unroll
            for (int mi = 0; mi < 4; mi++) {
                uint32_t off = (uint32_t)((wm + mi * 16 + (lane & 15)) * SPITCH +
                                          ks * 16 + ((lane >> 4) << 3)) * 2;
                uint32_t ah[4], al[4];
                LDSM_X4(ah[0], ah[1], ah[2], ah[3], aH + off);
                LDSM_X4(al[0], al[1], al[2], al[3], aL + off);
#pragma unroll
                for (int jn = 0; jn < 8; jn++) {
                    MMA16816(acc[mi][jn], ah, bh[jn][0], bh[jn][1]);
                    MMA16816(acc[mi][jn], ah, bl[jn][0], bl[jn][1]);
                    MMA16816(acc[mi][jn], al, bh[jn][0], bh[jn][1]);
                }
            }
        }
        if (t + 2 < NCH) { stage(t + 2, (t + 2) % 3); CP_COMMIT(); }
    }

    int qr = lane >> 2, qc = (lane & 3) * 2;
#pragma unroll
    for (int mi = 0; mi < 4; mi++) {
#pragma unroll
        for (int jn = 0; jn < 8; jn++) {
            int row = m0 + wm + mi * 16 + qr;
            int col = n0 + wn + jn * 8 + qc;
            *(float2*)&C[(size_t)row * DIM + col] =
                make_float2(acc[mi][jn][0], acc[mi][jn][1]);
            *(float2*)&C[(size_t)(row + 8) * DIM + col] =
                make_float2(acc[mi][jn][2], acc[mi][jn][3]);
        }
    }
}

// ---------------- HMMA flash attention (pipelined K/V prefetch) ----------------
#define PIT 136
#define FLASH_SMEM (6 * 128 * PIT * 2)

__global__ __launch_bounds__(256, 1)
void flash_mma(const __nv_bfloat16* __restrict__ Qhi, const __nv_bfloat16* __restrict__ Qlo,
               const __nv_bfloat16* __restrict__ Khi, const __nv_bfloat16* __restrict__ Klo,
               const __nv_bfloat16* __restrict__ Vhi, const __nv_bfloat16* __restrict__ Vlo,
               __nv_bfloat16* __restrict__ Oh, __nv_bfloat16* __restrict__ Ol)
{
    extern __shared__ __nv_bfloat16 smf[];
    __nv_bfloat16* sQh = smf;
    __nv_bfloat16* sQl = smf + 128 * PIT;
    __nv_bfloat16* sKh = smf + 2 * 128 * PIT;
    __nv_bfloat16* sKl = smf + 3 * 128 * PIT;
    __nv_bfloat16* sVh = smf + 4 * 128 * PIT;
    __nv_bfloat16* sVl = smf + 5 * 128 * PIT;

    int h  = blockIdx.y;
    int qt = (gridDim.x - 1) - blockIdx.x;
    int m0 = qt * 128;
    int kvh = h & 7;

    int tid = threadIdx.x, w = tid >> 5, lane = tid & 31;
    int gr = lane >> 2, qc = (lane & 3) * 2;

    auto stageK = [&](int n0) {
#pragma unroll
        for (int it = 0; it < 8; it++) {
            int idx = it * 256 + tid;
            int row = idx >> 4, c4 = idx & 15;
            size_t g = (size_t)(n0 + row) * KVD + kvh * HD + c4 * 8;
            uint32_t so = (uint32_t)(row * PIT + c4 * 8) * 2;
            cp16(smem_u32(sKh) + so, Khi + g);
            cp16(smem_u32(sKl) + so, Klo + g);
        }
    };
    auto stageV = [&](int n0) {
#pragma unroll
        for (int it = 0; it < 8; it++) {
            int idx = it * 256 + tid;
            int row = idx >> 4, c4 = idx & 15;
            size_t g = (size_t)(n0 + row) * KVD + kvh * HD + c4 * 8;
            uint32_t so = (uint32_t)(row * PIT + c4 * 8) * 2;
            cp16(smem_u32(sVh) + so, Vhi + g);
            cp16(smem_u32(sVl) + so, Vlo + g);
        }
    };

#pragma unroll
    for (int it = 0; it < 8; it++) {
        int idx = it * 256 + tid;
        int row = idx >> 4, c4 = idx & 15;
        *(uint4*)&sQh[row * PIT + c4 * 8] =
            *(const uint4*)(Qhi + (size_t)(m0 + row) * DIM + h * HD + c4 * 8);
        *(uint4*)&sQl[row * PIT + c4 * 8] =
            *(const uint4*)(Qlo + (size_t)(m0 + row) * DIM + h * HD + c4 * 8);
    }

    float o[16][4];
#pragma unroll
    for (int j = 0; j < 16; j++)
#pragma unroll
        for (int c = 0; c < 4; c++) o[j][c] = 0.f;
    float mrow[2] = {-INFINITY, -INFINITY};
    float lrow[2] = {0.f, 0.f};
    const float scale = 0.08838834764831845f;

    stageK(0); CP_COMMIT();
    stageV(0); CP_COMMIT();

    for (int kt = 0; kt <= qt; kt++) {
        CP_WAIT(1);          // K_kt complete (V_kt may be in flight)
        __syncthreads();

        float s[16][4];
#pragma unroll
        for (int j = 0; j < 16; j++)
#pragma unroll
            for (int c = 0; c < 4; c++) s[j][c] = 0.f;

#pragma unroll
        for (int g = 0; g < 4; g++) {
            uint32_t a0h[4], a1h[4], a0l[4], a1l[4];
            uint32_t offA = (uint32_t)((w * 16 + (lane & 15)) * PIT + g * 32 +
                                       ((lane >> 4) << 3)) * 2;
            LDSM_X4(a0h[0], a0h[1], a0h[2], a0h[3], smem_u32(sQh) + offA);
            LDSM_X4(a1h[0], a1h[1], a1h[2], a1h[3], smem_u32(sQh) + offA + 32);
            LDSM_X4(a0l[0], a0l[1], a0l[2], a0l[3], smem_u32(sQl) + offA);
            LDSM_X4(a1l[0], a1l[1], a1l[2], a1l[3], smem_u32(sQl) + offA + 32);
#pragma unroll
            for (int jn = 0; jn < 16; jn++) {
                uint32_t offB = (uint32_t)((jn * 8 + (lane & 7)) * PIT + g * 32 +
                                           ((lane >> 3) << 3)) * 2;
                uint32_t bh0, bh1, bh2, bh3, bl0, bl1, bl2, bl3;
                LDSM_X4(bh0, bh1, bh2, bh3, smem_u32(sKh) + offB);
                LDSM_X4(bl0, bl1, bl2, bl3, smem_u32(sKl) + offB);
                MMA16816(s[jn], a0h, bh0, bh1);
                MMA16816(s[jn], a1h, bh2, bh3);
                MMA16816(s[jn], a0h, bl0, bl1);
                MMA16816(s[jn], a1h, bl2, bl3);
                MMA16816(s[jn], a0l, bh0, bh1);
                MMA16816(s[jn], a1l, bh2, bh3);
            }
        }

        if (kt == qt) {
#pragma unroll
            for (int jn = 0; jn < 16; jn++) {
                int c0 = jn * 8 + qc;
                int r0 = w * 16 + gr;
                s[jn][0] = (c0     > r0    ) ? -1e30f : s[jn][0] * scale;
                s[jn][1] = (c0 + 1 > r0    ) ? -1e30f : s[jn][1] * scale;
                s[jn][2] = (c0     > r0 + 8) ? -1e30f : s[jn][2] * scale;
                s[jn][3] = (c0 + 1 > r0 + 8) ? -1e30f : s[jn][3] * scale;
            }
        } else {
#pragma unroll
            for (int jn = 0; jn < 16; jn++)
#pragma unroll
                for (int c = 0; c < 4; c++) s[jn][c] *= scale;
        }

#pragma unroll
        for (int half = 0; half < 2; half++) {
            int b = half * 2;
            float tmax = s[0][b];
#pragma unroll
            for (int jn = 0; jn < 16; jn++)
                tmax = fmaxf(tmax, fmaxf(s[jn][b], s[jn][b + 1]));
            tmax = fmaxf(tmax, __shfl_xor_sync(0xffffffffu, tmax, 1));
            tmax = fmaxf(tmax, __shfl_xor_sync(0xffffffffu, tmax, 2));

            float mnew = fmaxf(mrow[half], tmax);
            float alpha = exp_fast(mrow[half] - mnew);
            mrow[half] = mnew;

            float rsum = 0.f;
#pragma unroll
            for (int jn = 0; jn < 16; jn++) {
                float p0 = exp_fast(s[jn][b] - mnew);
                float p1 = exp_fast(s[jn][b + 1] - mnew);
                s[jn][b] = p0;
                s[jn][b + 1] = p1;
                rsum += p0 + p1;
            }
            rsum += __shfl_xor_sync(0xffffffffu, rsum, 1);
            rsum += __shfl_xor_sync(0xffffffffu, rsum, 2);

            lrow[half] = lrow[half] * alpha + rsum;
#pragma unroll
            for (int jn = 0; jn < 16; jn++) {
                o[jn][b]     *= alpha;
                o[jn][b + 1] *= alpha;
            }
        }

        uint32_t ph[8][4], pl[8][4];
#pragma unroll
        for (int ks = 0; ks < 8; ks++) {
#pragma unroll
            for (int q = 0; q < 4; q++) {
                int jn = 2 * ks + (q >> 1);
                int c  = (q & 1) * 2;
                float f0 = s[jn][c], f1 = s[jn][c + 1];
                uint32_t hp = pack_bf16x2(f0, f1);
                ph[ks][q] = hp;
                float h0 = __uint_as_float(hp << 16);
                float h1 = __uint_as_float(hp & 0xffff0000u);
                pl[ks][q] = pack_bf16x2(f0 - h0, f1 - h1);
            }
        }

        // K buffer free -> prefetch next K behind PV
        __syncthreads();
        if (kt < qt) { stageK((kt + 1) * 128); CP_COMMIT(); CP_WAIT(1); }
        else         { CP_WAIT(0); }
        __syncthreads();   // V_kt visible

#pragma unroll
        for (int ks = 0; ks < 8; ks++) {
#pragma unroll
            for (int jp = 0; jp < 8; jp++) {
                uint32_t offV = (uint32_t)((ks * 16 + (lane & 7) + ((lane >> 3) & 1) * 8) * PIT +
                                           jp * 16 + ((lane >> 4) << 3)) * 2;
                uint32_t vh0, vh1, vh2, vh3, vl0, vl1, vl2, vl3;
                LDSM_X4_T(vh0, vh1, vh2, vh3, smem_u32(sVh) + offV);
                LDSM_X4_T(vl0, vl1, vl2, vl3, smem_u32(sVl) + offV);
                MMA16816(o[2 * jp],     ph[ks], vh0, vh1);
                MMA16816(o[2 * jp + 1], ph[ks], vh2, vh3);
                MMA16816(o[2 * jp],     ph[ks], vl0, vl1);
                MMA16816(o[2 * jp + 1], ph[ks], vl2, vl3);
                MMA16816(o[2 * jp],     pl[ks], vh0, vh1);
                MMA16816(o[2 * jp + 1], pl[ks], vh2, vh3);
            }
        }

        // V buffer free -> prefetch next V behind next tile's S phase
        __syncthreads();
        if (kt < qt) { stageV((kt + 1) * 128); CP_COMMIT(); }
    }

    float inv0 = 1.f / lrow[0], inv1 = 1.f / lrow[1];
    int row0 = m0 + w * 16 + gr;
#pragma unroll
    for (int jn = 0; jn < 16; jn++) {
        int col = h * HD + jn * 8 + qc;
        float v0 = o[jn][0] * inv0, v1 = o[jn][1] * inv0;
        float v2 = o[jn][2] * inv1, v3 = o[jn][3] * inv1;
        uint32_t hw0 = pack_bf16x2(v0, v1);
        uint32_t lw0 = pack_bf16x2(v0 - __uint_as_float(hw0 << 16),
                                   v1 - __uint_as_float(hw0 & 0xffff0000u));
        uint32_t hw1 = pack_bf16x2(v2, v3);
        uint32_t lw1 = pack_bf16x2(v2 - __uint_as_float(hw1 << 16),
                                   v3 - __uint_as_float(hw1 & 0xffff0000u));
        *(uint32_t*)&Oh[(size_t)row0 * DIM + col]       = hw0;
        *(uint32_t*)&Ol[(size_t)row0 * DIM + col]       = lw0;
        *(uint32_t*)&Oh[(size_t)(row0 + 8) * DIM + col] = hw1;
        *(uint32_t*)&Ol[(size_t)(row0 + 8) * DIM + col] = lw1;
    }
}

// ---------------- launch ----------------
extern "C" void kernel_launch(void* const* d_in, const int* in_sizes, int n_in,
                              void* d_out, int out_size)
{
    const float* x  = (const float*)d_in[0];
    const float* wq = (const float*)d_in[1];
    const float* wk = (const float*)d_in[2];
    const float* wv = (const float*)d_in[3];
    const float* wo = (const float*)d_in[4];
    const float* fc = (const float*)d_in[5];
    const float* fs = (const float*)d_in[6];
    float* out = (float*)d_out;

    __nv_bfloat16 *pxhi, *pxlo, *pahi, *palo;
    __nv_bfloat16 *pqh, *pql, *pkh, *pkl, *pvh, *pvl;
    __nv_bfloat16 *pwqh, *pwql, *pwkh, *pwkl, *pwvh, *pwvl, *pwoh, *pwol;
    cudaGetSymbolAddress((void**)&pxhi, g_xhi);
    cudaGetSymbolAddress((void**)&pxlo, g_xlo);
    cudaGetSymbolAddress((void**)&pahi, g_atthi);
    cudaGetSymbolAddress((void**)&palo, g_attlo);
    cudaGetSymbolAddress((void**)&pqh,  g_qhi);
    cudaGetSymbolAddress((void**)&pql,  g_qlo);
    cudaGetSymbolAddress((void**)&pkh,  g_khi);
    cudaGetSymbolAddress((void**)&pkl,  g_klo);
    cudaGetSymbolAddress((void**)&pvh,  g_vhi);
    cudaGetSymbolAddress((void**)&pvl,  g_vlo);
    cudaGetSymbolAddress((void**)&pwqh, g_wqT_hi);
    cudaGetSymbolAddress((void**)&pwql, g_wqT_lo);
    cudaGetSymbolAddress((void**)&pwkh, g_wkT_hi);
    cudaGetSymbolAddress((void**)&pwkl, g_wkT_lo);
    cudaGetSymbolAddress((void**)&pwvh, g_wvT_hi);
    cudaGetSymbolAddress((void**)&pwvl, g_wvT_lo);
    cudaGetSymbolAddress((void**)&pwoh, g_woT_hi);
    cudaGetSymbolAddress((void**)&pwol, g_woT_lo);

    static bool attr_set = false;
    if (!attr_set) {
        cudaFuncSetAttribute(flash_mma, cudaFuncAttributeMaxDynamicSharedMemorySize,
                             FLASH_SMEM);
        cudaFuncSetAttribute(gemm_qkv, cudaFuncAttributeMaxDynamicSharedMemorySize,
                             QKV_SMEM);
        cudaFuncSetAttribute(gemm_out, cudaFuncAttributeMaxDynamicSharedMemorySize,
                             QKV_SMEM);
        attr_set = true;
    }

    transpose_split<<<dim3(DIM / 32, DIM / 32), 256>>>(wq, pwqh, pwql, DIM, DIM);
    transpose_split<<<dim3(KVD / 32, DIM / 32), 256>>>(wk, pwkh, pwkl, DIM, KVD);
    transpose_split<<<dim3(KVD / 32, DIM / 32), 256>>>(wv, pwvh, pwvl, DIM, KVD);
    transpose_split<<<dim3(DIM / 32, DIM / 32), 256>>>(wo, pwoh, pwol, DIM, DIM);
    split_rows<<<(SQ * DIM) / 256, 256>>>(x, pxhi, pxlo);

    gemm_qkv<<<dim3(24, SQ / 128), 256, QKV_SMEM>>>(
        pxhi, pxlo, pwqh, pwql, pwkh, pwkl, pwvh, pwvl,
        pqh, pql, pkh, pkl, pvh, pvl, fc, fs);

    flash_mma<<<dim3(SQ / 128, NH), 256, FLASH_SMEM>>>(pqh, pql, pkh, pkl, pvh, pvl,
                                                       pahi, palo);

    gemm_out<<<dim3(DIM / 256, SQ / 128), 256, QKV_SMEM>>>(pahi, palo, pwoh, pwol, out);
}

// round 17
// speedup vs baseline: 1.0160x; 1.0160x over previous
#include <cuda_runtime.h>
#include <cuda_bf16.h>
#include <math.h>
#include <stdint.h>

#define SQ   2048
#define DIM  4096
#define NH   32
#define NKVH 8
#define HD   128
#define KVD  (NKVH*HD)   // 1024
#define KTOT 4096

// ---------------- scratch ----------------
__device__ __align__(16) __nv_bfloat16 g_xhi[(size_t)SQ * DIM];
__device__ __align__(16) __nv_bfloat16 g_xlo[(size_t)SQ * DIM];
__device__ __align__(16) __nv_bfloat16 g_atthi[(size_t)SQ * DIM];
__device__ __align__(16) __nv_bfloat16 g_attlo[(size_t)SQ * DIM];
__device__ __align__(16) __nv_bfloat16 g_qhi[(size_t)SQ * DIM];
__device__ __align__(16) __nv_bfloat16 g_qlo[(size_t)SQ * DIM];
__device__ __align__(16) __nv_bfloat16 g_khi[(size_t)SQ * KVD];
__device__ __align__(16) __nv_bfloat16 g_klo[(size_t)SQ * KVD];
__device__ __align__(16) __nv_bfloat16 g_vhi[(size_t)SQ * KVD];
__device__ __align__(16) __nv_bfloat16 g_vlo[(size_t)SQ * KVD];
__device__ __align__(16) __nv_bfloat16 g_wqT_hi[(size_t)DIM * DIM];
__device__ __align__(16) __nv_bfloat16 g_wqT_lo[(size_t)DIM * DIM];
__device__ __align__(16) __nv_bfloat16 g_wkT_hi[(size_t)KVD * DIM];
__device__ __align__(16) __nv_bfloat16 g_wkT_lo[(size_t)KVD * DIM];
__device__ __align__(16) __nv_bfloat16 g_wvT_hi[(size_t)KVD * DIM];
__device__ __align__(16) __nv_bfloat16 g_wvT_lo[(size_t)KVD * DIM];
__device__ __align__(16) __nv_bfloat16 g_woT_hi[(size_t)DIM * DIM];
__device__ __align__(16) __nv_bfloat16 g_woT_lo[(size_t)DIM * DIM];

__device__ __forceinline__ uint32_t smem_u32(const void* p) {
    return (uint32_t)__cvta_generic_to_shared(p);
}
#define LDSM_X4(r0, r1, r2, r3, addr)                                          \
    asm volatile("ldmatrix.sync.aligned.m8n8.x4.shared.b16 {%0,%1,%2,%3}, [%4];" \
                 : "=r"(r0), "=r"(r1), "=r"(r2), "=r"(r3) : "r"(addr))
#define LDSM_X4_T(r0, r1, r2, r3, addr)                                        \
    asm volatile("ldmatrix.sync.aligned.m8n8.x4.trans.shared.b16 {%0,%1,%2,%3}, [%4];" \
                 : "=r"(r0), "=r"(r1), "=r"(r2), "=r"(r3) : "r"(addr))
#define MMA16816(c, a, b0_, b1_)                                               \
    asm volatile("mma.sync.aligned.m16n8k16.row.col.f32.bf16.bf16.f32 "        \
                 "{%0,%1,%2,%3}, {%4,%5,%6,%7}, {%8,%9}, {%0,%1,%2,%3};"       \
                 : "+f"((c)[0]), "+f"((c)[1]), "+f"((c)[2]), "+f"((c)[3])      \
                 : "r"((a)[0]), "r"((a)[1]), "r"((a)[2]), "r"((a)[3]),         \
                   "r"(b0_), "r"(b1_))
__device__ __forceinline__ void cp16(uint32_t saddr, const void* g) {
    asm volatile("cp.async.cg.shared.global [%0], [%1], 16;"
                 :: "r"(saddr), "l"(g) : "memory");
}
#define CP_COMMIT() asm volatile("cp.async.commit_group;" ::: "memory")
#define CP_WAIT(n)  asm volatile("cp.async.wait_group %0;" :: "n"(n) : "memory")

__device__ __forceinline__ uint32_t pack_bf16x2(float lo, float hi) {
    uint32_t r;
    asm("cvt.rn.bf16x2.f32 %0, %1, %2;" : "=r"(r) : "f"(hi), "f"(lo));
    return r;
}
__device__ __forceinline__ float exp_fast(float x) {
    float t = fmaxf(x * 1.4426950408889634f, -126.0f);
    float fi = floorf(t);
    float f = t - fi;
    float p = fmaf(f, 0.0013333558f, 0.0096181291f);
    p = fmaf(f, p, 0.0555041087f);
    p = fmaf(f, p, 0.2402265069f);
    p = fmaf(f, p, 0.6931471806f);
    p = fmaf(f, p, 1.0f);
    int i = (int)fi;
    return __int_as_float((uint32_t)(i + 127) << 23) * p;
}

// ---------------- conversion kernels ----------------
__global__ __launch_bounds__(256)
void split_rows(const float* __restrict__ X, __nv_bfloat16* __restrict__ hi,
                __nv_bfloat16* __restrict__ lo)
{
    size_t i = (size_t)blockIdx.x * 256 + threadIdx.x;
    float v = X[i];
    __nv_bfloat16 h = __float2bfloat16(v);
    hi[i] = h;
    lo[i] = __float2bfloat16(v - __bfloat162float(h));
}

__global__ __launch_bounds__(256)
void transpose_split(const float* __restrict__ W, __nv_bfloat16* __restrict__ Thi,
                     __nv_bfloat16* __restrict__ Tlo, int K, int N)
{
    __shared__ float tile[32][33];
    int n0 = blockIdx.x * 32, k0 = blockIdx.y * 32;
    int tx = threadIdx.x & 31, ty = threadIdx.x >> 5;
#pragma unroll
    for (int j = 0; j < 4; j++)
        tile[ty + j * 8][tx] = W[(size_t)(k0 + ty + j * 8) * N + n0 + tx];
    __syncthreads();
#pragma unroll
    for (int j = 0; j < 4; j++) {
        float v = tile[tx][ty + j * 8];
        __nv_bfloat16 h = __float2bfloat16(v);
        __nv_bfloat16 l = __float2bfloat16(v - __bfloat162float(h));
        size_t o = (size_t)(n0 + ty + j * 8) * K + k0 + tx;
        Thi[o] = h;
        Tlo[o] = l;
    }
}

// ---------------- QKV mega-GEMM: CTA 128x256, warps 64x64, 3-stage cp.async ----
#define SPITCH 40
#define AOFF_L (128 * SPITCH)
#define BOFF_H (2 * 128 * SPITCH)
#define BOFF_L (2 * 128 * SPITCH + 256 * SPITCH)
#define SLOT_EL (SPITCH * (128 + 128 + 256 + 256))
#define QKV_SMEM (3 * SLOT_EL * 2)

struct QkvOut {
    const __nv_bfloat16 *bh, *bl;
    __nv_bfloat16 *oh, *ol;
    int nloc, ldo, rope;
};

__global__ void __launch_bounds__(256, 1)
gemm_qkv(const __nv_bfloat16* __restrict__ Ahi, const __nv_bfloat16* __restrict__ Alo,
         const __nv_bfloat16* __restrict__ Wqh, const __nv_bfloat16* __restrict__ Wql,
         const __nv_bfloat16* __restrict__ Wkh, const __nv_bfloat16* __restrict__ Wkl,
         const __nv_bfloat16* __restrict__ Wvh, const __nv_bfloat16* __restrict__ Wvl,
         __nv_bfloat16* __restrict__ Qh, __nv_bfloat16* __restrict__ Ql,
         __nv_bfloat16* __restrict__ Kh, __nv_bfloat16* __restrict__ Kl,
         __nv_bfloat16* __restrict__ Vh, __nv_bfloat16* __restrict__ Vl,
         const float* __restrict__ fc, const float* __restrict__ fs)
{
    extern __shared__ __nv_bfloat16 dsm[];
    int tid = threadIdx.x, wid = tid >> 5, lane = tid & 31;
    int m0 = blockIdx.y * 128;
    int xb = blockIdx.x;

    QkvOut oc;
    if (xb < 16)      { oc = {Wqh, Wql, Qh, Ql, xb * 256, DIM, 1}; }
    else if (xb < 20) { oc = {Wkh, Wkl, Kh, Kl, (xb - 16) * 256, KVD, 1}; }
    else              { oc = {Wvh, Wvl, Vh, Vl, (xb - 20) * 256, KVD, 0}; }

    int wm = (wid & 1) * 64, wn = (wid >> 1) * 64;
    uint32_t smbase = smem_u32(dsm);
    int arow = tid >> 1, ahalf = (tid & 1) * 16;

    float acc[4][8][4];
#pragma unroll
    for (int i = 0; i < 4; i++)
#pragma unroll
        for (int j = 0; j < 8; j++)
#pragma unroll
            for (int c = 0; c < 4; c++) acc[i][j][c] = 0.f;

    auto stage = [&](int c, int s) {
        uint32_t sb = smbase + (uint32_t)s * (SLOT_EL * 2);
        size_t gA = (size_t)(m0 + arow) * KTOT + c * 32 + ahalf;
        uint32_t ao = (uint32_t)(arow * SPITCH + ahalf) * 2;
        cp16(sb + ao,                    Ahi + gA);
        cp16(sb + ao + 16,               Ahi + gA + 8);
        cp16(sb + AOFF_L * 2 + ao,       Alo + gA);
        cp16(sb + AOFF_L * 2 + ao + 16,  Alo + gA + 8);
#pragma unroll
        for (int j = 0; j < 2; j++) {
            int brow = arow + j * 128;
            size_t gB = (size_t)(oc.nloc + brow) * KTOT + c * 32 + ahalf;
            uint32_t bo = (uint32_t)(brow * SPITCH + ahalf) * 2;
            cp16(sb + BOFF_H * 2 + bo,      oc.bh + gB);
            cp16(sb + BOFF_H * 2 + bo + 16, oc.bh + gB + 8);
            cp16(sb + BOFF_L * 2 + bo,      oc.bl + gB);
            cp16(sb + BOFF_L * 2 + bo + 16, oc.bl + gB + 8);
        }
    };

    const int NCH = KTOT / 32;  // 128
    stage(0, 0); CP_COMMIT();
    stage(1, 1); CP_COMMIT();

    for (int t = 0; t < NCH; t++) {
        CP_WAIT(1);
        __syncthreads();
        int slot = t % 3;
        uint32_t sb = smbase + (uint32_t)slot * (SLOT_EL * 2);
        uint32_t aH = sb, aL = sb + AOFF_L * 2, bH = sb + BOFF_H * 2, bL = sb + BOFF_L * 2;

#pragma unroll
        for (int ks = 0; ks < 2; ks++) {
            uint32_t bh[8][2], bl[8][2];
#pragma unroll
            for (int jp = 0; jp < 4; jp++) {
                uint32_t off = (uint32_t)((wn + jp * 16 + (lane & 15)) * SPITCH +
                                          ks * 16 + ((lane >> 4) << 3)) * 2;
                uint32_t h0, h1, h2, h3, l0, l1, l2, l3;
                LDSM_X4(h0, h1, h2, h3, bH + off);
                LDSM_X4(l0, l1, l2, l3, bL + off);
                bh[2*jp][0] = h0; bh[2*jp][1] = h2;
                bh[2*jp+1][0] = h1; bh[2*jp+1][1] = h3;
                bl[2*jp][0] = l0; bl[2*jp][1] = l2;
                bl[2*jp+1][0] = l1; bl[2*jp+1][1] = l3;
            }
#pragma unroll
            for (int mi = 0; mi < 4; mi++) {
                uint32_t off = (uint32_t)((wm + mi * 16 + (lane & 15)) * SPITCH +
                                          ks * 16 + ((lane >> 4) << 3)) * 2;
                uint32_t ah[4], al[4];
                LDSM_X4(ah[0], ah[1], ah[2], ah[3], aH + off);
                LDSM_X4(al[0], al[1], al[2], al[3], aL + off);
#pragma unroll
                for (int jn = 0; jn < 8; jn++) {
                    MMA16816(acc[mi][jn], ah, bh[jn][0], bh[jn][1]);
                    MMA16816(acc[mi][jn], ah, bl[jn][0], bl[jn][1]);
                    MMA16816(acc[mi][jn], al, bh[jn][0], bh[jn][1]);
                }
            }
        }
        // 3 slots: staging (t+2)%3 never aliases any readable slot -> no 2nd sync
        if (t + 2 < NCH) { stage(t + 2, (t + 2) % 3); CP_COMMIT(); }
    }

    int qr = lane >> 2, qc = (lane & 3) * 2;
#pragma unroll
    for (int mi = 0; mi < 4; mi++) {
#pragma unroll
        for (int jn = 0; jn < 8; jn++) {
            int r0 = m0 + wm + mi * 16 + qr;
            int cl = oc.nloc + wn + jn * 8 + qc;
            float v00 = acc[mi][jn][0], v01 = acc[mi][jn][1];
            float v10 = acc[mi][jn][2], v11 = acc[mi][jn][3];
            if (oc.rope) {
                int p = (cl & 127) >> 1;
                float c0 = fc[r0 * 64 + p],       s0 = fs[r0 * 64 + p];
                float c1 = fc[(r0 + 8) * 64 + p], s1 = fs[(r0 + 8) * 64 + p];
                float e0 = v00 * c0 - v01 * s0, o0 = v01 * c0 + v00 * s0;
                float e1 = v10 * c1 - v11 * s1, o1 = v11 * c1 + v10 * s1;
                v00 = e0; v01 = o0; v10 = e1; v11 = o1;
            }
            uint32_t hw0 = pack_bf16x2(v00, v01);
            uint32_t lw0 = pack_bf16x2(v00 - __uint_as_float(hw0 << 16),
                                       v01 - __uint_as_float(hw0 & 0xffff0000u));
            uint32_t hw1 = pack_bf16x2(v10, v11);
            uint32_t lw1 = pack_bf16x2(v10 - __uint_as_float(hw1 << 16),
                                       v11 - __uint_as_float(hw1 & 0xffff0000u));
            *(uint32_t*)&oc.oh[(size_t)r0 * oc.ldo + cl]       = hw0;
            *(uint32_t*)&oc.ol[(size_t)r0 * oc.ldo + cl]       = lw0;
            *(uint32_t*)&oc.oh[(size_t)(r0 + 8) * oc.ldo + cl] = hw1;
            *(uint32_t*)&oc.ol[(size_t)(r0 + 8) * oc.ldo + cl] = lw1;
        }
    }
}

// ---------------- O projection ----------------
__global__ void __launch_bounds__(256, 1)
gemm_out(const __nv_bfloat16* __restrict__ Ahi, const __nv_bfloat16* __restrict__ Alo,
         const __nv_bfloat16* __restrict__ Bhi, const __nv_bfloat16* __restrict__ Blo,
         float* __restrict__ C)
{
    extern __shared__ __nv_bfloat16 dsm[];
    int tid = threadIdx.x, wid = tid >> 5, lane = tid & 31;
    int m0 = blockIdx.y * 128, n0 = blockIdx.x * 256;
    int wm = (wid & 1) * 64, wn = (wid >> 1) * 64;
    uint32_t smbase = smem_u32(dsm);
    int arow = tid >> 1, ahalf = (tid & 1) * 16;

    float acc[4][8][4];
#pragma unroll
    for (int i = 0; i < 4; i++)
#pragma unroll
        for (int j = 0; j < 8; j++)
#pragma unroll
            for (int c = 0; c < 4; c++) acc[i][j][c] = 0.f;

    auto stage = [&](int c, int s) {
        uint32_t sb = smbase + (uint32_t)s * (SLOT_EL * 2);
        size_t gA = (size_t)(m0 + arow) * KTOT + c * 32 + ahalf;
        uint32_t ao = (uint32_t)(arow * SPITCH + ahalf) * 2;
        cp16(sb + ao,                   Ahi + gA);
        cp16(sb + ao + 16,              Ahi + gA + 8);
        cp16(sb + AOFF_L * 2 + ao,      Alo + gA);
        cp16(sb + AOFF_L * 2 + ao + 16, Alo + gA + 8);
#pragma unroll
        for (int j = 0; j < 2; j++) {
            int brow = arow + j * 128;
            size_t gB = (size_t)(n0 + brow) * KTOT + c * 32 + ahalf;
            uint32_t bo = (uint32_t)(brow * SPITCH + ahalf) * 2;
            cp16(sb + BOFF_H * 2 + bo,      Bhi + gB);
            cp16(sb + BOFF_H * 2 + bo + 16, Bhi + gB + 8);
            cp16(sb + BOFF_L * 2 + bo,      Blo + gB);
            cp16(sb + BOFF_L * 2 + bo + 16, Blo + gB + 8);
        }
    };

    const int NCH = KTOT / 32;
    stage(0, 0); CP_COMMIT();
    stage(1, 1); CP_COMMIT();

    for (int t = 0; t < NCH; t++) {
        CP_WAIT(1);
        __syncthreads();
        int slot = t % 3;
        uint32_t sb = smbase + (uint32_t)slot * (SLOT_EL * 2);
        uint32_t aH = sb, aL = sb + AOFF_L * 2, bH = sb + BOFF_H * 2, bL = sb + BOFF_L * 2;

#pragma unroll
        for (int ks = 0; ks < 2; ks++) {
            uint32_t bh[8][2], bl[8][2];
#pragma unroll
            for (int jp = 0; jp < 4; jp++) {
                uint32_t off = (uint32_t)((wn + jp * 16 + (lane & 15)) * SPITCH +
                                          ks * 16 + ((lane >> 4) << 3)) * 2;
                uint32_t h0, h1, h2, h3, l0, l1, l2, l3;
                LDSM_X4(h0, h1, h2, h3, bH + off);
                LDSM_X4(l0, l1, l2, l3, bL + off);
                bh[2*jp][0] = h0; bh[2*jp][1] = h2;
                bh[2*jp+1][0] = h1; bh[2*jp+1][1] = h3;
                bl[2*jp][0] = l0; bl[2*jp][1] = l2;
                bl[2*jp+1][0] = l1; bl[2*jp+1][1] = l3;
            }
#pragma unroll
            for (int mi = 0; mi < 4; mi++) {
                uint32_t off = (uint32_t)((wm + mi * 16 + (lane & 15)) * SPITCH +
                                          ks * 16 + ((lane >> 4) << 3)) * 2;
                uint32_t ah[4], al[4];
                LDSM_X4(ah[0], ah[1], ah[2], ah[3], aH + off);
                LDSM_X4(al[0], al[1], al[2], al[3], aL + off);
#pragma unroll
                for (int jn = 0; jn < 8; jn++) {
                    MMA16816(acc[mi][jn], ah, bh[jn][0], bh[jn][1]);
                    MMA16816(acc[mi][jn], ah, bl[jn][0], bl[jn][1]);
                    MMA16816(acc[mi][jn], al, bh[jn][0], bh[jn][1]);
                }
            }
        }
        if (t + 2 < NCH) { stage(t + 2, (t + 2) % 3); CP_COMMIT(); }
    }

    int qr = lane >> 2, qc = (lane & 3) * 2;
#pragma unroll
    for (int mi = 0; mi < 4; mi++) {
#pragma unroll
        for (int jn = 0; jn < 8; jn++) {
            int row = m0 + wm + mi * 16 + qr;
            int col = n0 + wn + jn * 8 + qc;
            *(float2*)&C[(size_t)row * DIM + col] =
                make_float2(acc[mi][jn][0], acc[mi][jn][1]);
            *(float2*)&C[(size_t)(row + 8) * DIM + col] =
                make_float2(acc[mi][jn][2], acc[mi][jn][3]);
        }
    }
}

// ---------------- HMMA flash attention (R11 schedule) ----------------
#define PIT 136
#define FLASH_SMEM (6 * 128 * PIT * 2)

__global__ __launch_bounds__(256, 1)
void flash_mma(const __nv_bfloat16* __restrict__ Qhi, const __nv_bfloat16* __restrict__ Qlo,
               const __nv_bfloat16* __restrict__ Khi, const __nv_bfloat16* __restrict__ Klo,
               const __nv_bfloat16* __restrict__ Vhi, const __nv_bfloat16* __restrict__ Vlo,
               __nv_bfloat16* __restrict__ Oh, __nv_bfloat16* __restrict__ Ol)
{
    extern __shared__ __nv_bfloat16 smf[];
    __nv_bfloat16* sQh = smf;
    __nv_bfloat16* sQl = smf + 128 * PIT;
    __nv_bfloat16* sKh = smf + 2 * 128 * PIT;
    __nv_bfloat16* sKl = smf + 3 * 128 * PIT;
    __nv_bfloat16* sVh = smf + 4 * 128 * PIT;
    __nv_bfloat16* sVl = smf + 5 * 128 * PIT;

    int h  = blockIdx.y;
    int qt = (gridDim.x - 1) - blockIdx.x;
    int m0 = qt * 128;
    int kvh = h & 7;

    int tid = threadIdx.x, w = tid >> 5, lane = tid & 31;
    int gr = lane >> 2, qc = (lane & 3) * 2;

#pragma unroll
    for (int it = 0; it < 8; it++) {
        int idx = it * 256 + tid;
        int row = idx >> 4, c4 = idx & 15;
        *(uint4*)&sQh[row * PIT + c4 * 8] =
            *(const uint4*)(Qhi + (size_t)(m0 + row) * DIM + h * HD + c4 * 8);
        *(uint4*)&sQl[row * PIT + c4 * 8] =
            *(const uint4*)(Qlo + (size_t)(m0 + row) * DIM + h * HD + c4 * 8);
    }
    __syncthreads();

    float o[16][4];
#pragma unroll
    for (int j = 0; j < 16; j++)
#pragma unroll
        for (int c = 0; c < 4; c++) o[j][c] = 0.f;
    float mrow[2] = {-INFINITY, -INFINITY};
    float lrow[2] = {0.f, 0.f};
    const float scale = 0.08838834764831845f;

    for (int kt = 0; kt <= qt; kt++) {
        int n0 = kt * 128;
#pragma unroll
        for (int it = 0; it < 8; it++) {
            int idx = it * 256 + tid;
            int row = idx >> 4, c4 = idx & 15;
            size_t g = (size_t)(n0 + row) * KVD + kvh * HD + c4 * 8;
            uint32_t so = (uint32_t)(row * PIT + c4 * 8) * 2;
            cp16(smem_u32(sKh) + so, Khi + g);
            cp16(smem_u32(sKl) + so, Klo + g);
        }
        CP_COMMIT();
#pragma unroll
        for (int it = 0; it < 8; it++) {
            int idx = it * 256 + tid;
            int row = idx >> 4, c4 = idx & 15;
            size_t g = (size_t)(n0 + row) * KVD + kvh * HD + c4 * 8;
            uint32_t so = (uint32_t)(row * PIT + c4 * 8) * 2;
            cp16(smem_u32(sVh) + so, Vhi + g);
            cp16(smem_u32(sVl) + so, Vlo + g);
        }
        CP_COMMIT();

        CP_WAIT(1);
        __syncthreads();

        float s[16][4];
#pragma unroll
        for (int j = 0; j < 16; j++)
#pragma unroll
            for (int c = 0; c < 4; c++) s[j][c] = 0.f;

#pragma unroll
        for (int g = 0; g < 4; g++) {
            uint32_t a0h[4], a1h[4], a0l[4], a1l[4];
            uint32_t offA = (uint32_t)((w * 16 + (lane & 15)) * PIT + g * 32 +
                                       ((lane >> 4) << 3)) * 2;
            LDSM_X4(a0h[0], a0h[1], a0h[2], a0h[3], smem_u32(sQh) + offA);
            LDSM_X4(a1h[0], a1h[1], a1h[2], a1h[3], smem_u32(sQh) + offA + 32);
            LDSM_X4(a0l[0], a0l[1], a0l[2], a0l[3], smem_u32(sQl) + offA);
            LDSM_X4(a1l[0], a1l[1], a1l[2], a1l[3], smem_u32(sQl) + offA + 32);
#pragma unroll
            for (int jn = 0; jn < 16; jn++) {
                uint32_t offB = (uint32_t)((jn * 8 + (lane & 7)) * PIT + g * 32 +
                                           ((lane >> 3) << 3)) * 2;
                uint32_t bh0, bh1, bh2, bh3, bl0, bl1, bl2, bl3;
                LDSM_X4(bh0, bh1, bh2, bh3, smem_u32(sKh) + offB);
                LDSM_X4(bl0, bl1, bl2, bl3, smem_u32(sKl) + offB);
                MMA16816(s[jn], a0h, bh0, bh1);
                MMA16816(s[jn], a1h, bh2, bh3);
                MMA16816(s[jn], a0h, bl0, bl1);
                MMA16816(s[jn], a1h, bl2, bl3);
                MMA16816(s[jn], a0l, bh0, bh1);
                MMA16816(s[jn], a1l, bh2, bh3);
            }
        }

        if (kt == qt) {
#pragma unroll
            for (int jn = 0; jn < 16; jn++) {
                int c0 = jn * 8 + qc;
                int r0 = w * 16 + gr;
                s[jn][0] = (c0     > r0    ) ? -1e30f : s[jn][0] * scale;
                s[jn][1] = (c0 + 1 > r0    ) ? -1e30f : s[jn][1] * scale;
                s[jn][2] = (c0     > r0 + 8) ? -1e30f : s[jn][2] * scale;
                s[jn][3] = (c0 + 1 > r0 + 8) ? -1e30f : s[jn][3] * scale;
            }
        } else {
#pragma unroll
            for (int jn = 0; jn < 16; jn++)
#pragma unroll
                for (int c = 0; c < 4; c++) s[jn][c] *= scale;
        }

#pragma unroll
        for (int half = 0; half < 2; half++) {
            int b = half * 2;
            float tmax = s[0][b];
#pragma unroll
            for (int jn = 0; jn < 16; jn++)
                tmax = fmaxf(tmax, fmaxf(s[jn][b], s[jn][b + 1]));
            tmax = fmaxf(tmax, __shfl_xor_sync(0xffffffffu, tmax, 1));
            tmax = fmaxf(tmax, __shfl_xor_sync(0xffffffffu, tmax, 2));

            float mnew = fmaxf(mrow[half], tmax);
            float alpha = exp_fast(mrow[half] - mnew);
            mrow[half] = mnew;

            float rsum = 0.f;
#pragma unroll
            for (int jn = 0; jn < 16; jn++) {
                float p0 = exp_fast(s[jn][b] - mnew);
                float p1 = exp_fast(s[jn][b + 1] - mnew);
                s[jn][b] = p0;
                s[jn][b + 1] = p1;
                rsum += p0 + p1;
            }
            rsum += __shfl_xor_sync(0xffffffffu, rsum, 1);
            rsum += __shfl_xor_sync(0xffffffffu, rsum, 2);

            lrow[half] = lrow[half] * alpha + rsum;
#pragma unroll
            for (int jn = 0; jn < 16; jn++) {
                o[jn][b]     *= alpha;
                o[jn][b + 1] *= alpha;
            }
        }

        uint32_t ph[8][4], pl[8][4];
#pragma unroll
        for (int ks = 0; ks < 8; ks++) {
#pragma unroll
            for (int q = 0; q < 4; q++) {
                int jn = 2 * ks + (q >> 1);
                int c  = (q & 1) * 2;
                float f0 = s[jn][c], f1 = s[jn][c + 1];
                uint32_t hp = pack_bf16x2(f0, f1);
                ph[ks][q] = hp;
                float h0 = __uint_as_float(hp << 16);
                float h1 = __uint_as_float(hp & 0xffff0000u);
                pl[ks][q] = pack_bf16x2(f0 - h0, f1 - h1);
            }
        }

        CP_WAIT(0);
        __syncthreads();

#pragma unroll
        for (int ks = 0; ks < 8; ks++) {
#pragma unroll
            for (int jp = 0; jp < 8; jp++) {
                uint32_t offV = (uint32_t)((ks * 16 + (lane & 7) + ((lane >> 3) & 1) * 8) * PIT +
                                           jp * 16 + ((lane >> 4) << 3)) * 2;
                uint32_t vh0, vh1, vh2, vh3, vl0, vl1, vl2, vl3;
                LDSM_X4_T(vh0, vh1, vh2, vh3, smem_u32(sVh) + offV);
                LDSM_X4_T(vl0, vl1, vl2, vl3, smem_u32(sVl) + offV);
                MMA16816(o[2 * jp],     ph[ks], vh0, vh1);
                MMA16816(o[2 * jp + 1], ph[ks], vh2, vh3);
                MMA16816(o[2 * jp],     ph[ks], vl0, vl1);
                MMA16816(o[2 * jp + 1], ph[ks], vl2, vl3);
                MMA16816(o[2 * jp],     pl[ks], vh0, vh1);
                MMA16816(o[2 * jp + 1], pl[ks], vh2, vh3);
            }
        }
        __syncthreads();
    }

    float inv0 = 1.f / lrow[0], inv1 = 1.f / lrow[1];
    int row0 = m0 + w * 16 + gr;
#pragma unroll
    for (int jn = 0; jn < 16; jn++) {
        int col = h * HD + jn * 8 + qc;
        float v0 = o[jn][0] * inv0, v1 = o[jn][1] * inv0;
        float v2 = o[jn][2] * inv1, v3 = o[jn][3] * inv1;
        uint32_t hw0 = pack_bf16x2(v0, v1);
        uint32_t lw0 = pack_bf16x2(v0 - __uint_as_float(hw0 << 16),
                                   v1 - __uint_as_float(hw0 & 0xffff0000u));
        uint32_t hw1 = pack_bf16x2(v2, v3);
        uint32_t lw1 = pack_bf16x2(v2 - __uint_as_float(hw1 << 16),
                                   v3 - __uint_as_float(hw1 & 0xffff0000u));
        *(uint32_t*)&Oh[(size_t)row0 * DIM + col]       = hw0;
        *(uint32_t*)&Ol[(size_t)row0 * DIM + col]       = lw0;
        *(uint32_t*)&Oh[(size_t)(row0 + 8) * DIM + col] = hw1;
        *(uint32_t*)&Ol[(size_t)(row0 + 8) * DIM + col] = lw1;
    }
}

// ---------------- launch ----------------
extern "C" void kernel_launch(void* const* d_in, const int* in_sizes, int n_in,
                              void* d_out, int out_size)
{
    const float* x  = (const float*)d_in[0];
    const float* wq = (const float*)d_in[1];
    const float* wk = (const float*)d_in[2];
    const float* wv = (const float*)d_in[3];
    const float* wo = (const float*)d_in[4];
    const float* fc = (const float*)d_in[5];
    const float* fs = (const float*)d_in[6];
    float* out = (float*)d_out;

    __nv_bfloat16 *pxhi, *pxlo, *pahi, *palo;
    __nv_bfloat16 *pqh, *pql, *pkh, *pkl, *pvh, *pvl;
    __nv_bfloat16 *pwqh, *pwql, *pwkh, *pwkl, *pwvh, *pwvl, *pwoh, *pwol;
    cudaGetSymbolAddress((void**)&pxhi, g_xhi);
    cudaGetSymbolAddress((void**)&pxlo, g_xlo);
    cudaGetSymbolAddress((void**)&pahi, g_atthi);
    cudaGetSymbolAddress((void**)&palo, g_attlo);
    cudaGetSymbolAddress((void**)&pqh,  g_qhi);
    cudaGetSymbolAddress((void**)&pql,  g_qlo);
    cudaGetSymbolAddress((void**)&pkh,  g_khi);
    cudaGetSymbolAddress((void**)&pkl,  g_klo);
    cudaGetSymbolAddress((void**)&pvh,  g_vhi);
    cudaGetSymbolAddress((void**)&pvl,  g_vlo);
    cudaGetSymbolAddress((void**)&pwqh, g_wqT_hi);
    cudaGetSymbolAddress((void**)&pwql, g_wqT_lo);
    cudaGetSymbolAddress((void**)&pwkh, g_wkT_hi);
    cudaGetSymbolAddress((void**)&pwkl, g_wkT_lo);
    cudaGetSymbolAddress((void**)&pwvh, g_wvT_hi);
    cudaGetSymbolAddress((void**)&pwvl, g_wvT_lo);
    cudaGetSymbolAddress((void**)&pwoh, g_woT_hi);
    cudaGetSymbolAddress((void**)&pwol, g_woT_lo);

    static bool attr_set = false;
    if (!attr_set) {
        cudaFuncSetAttribute(flash_mma, cudaFuncAttributeMaxDynamicSharedMemorySize,
                             FLASH_SMEM);
        cudaFuncSetAttribute(gemm_qkv, cudaFuncAttributeMaxDynamicSharedMemorySize,
                             QKV_SMEM);
        cudaFuncSetAttribute(gemm_out, cudaFuncAttributeMaxDynamicSharedMemorySize,
                             QKV_SMEM);
        attr_set = true;
    }

    transpose_split<<<dim3(DIM / 32, DIM / 32), 256>>>(wq, pwqh, pwql, DIM, DIM);
    transpose_split<<<dim3(KVD / 32, DIM / 32), 256>>>(wk, pwkh, pwkl, DIM, KVD);
    transpose_split<<<dim3(KVD / 32, DIM / 32), 256>>>(wv, pwvh, pwvl, DIM, KVD);
    transpose_split<<<dim3(DIM / 32, DIM / 32), 256>>>(wo, pwoh, pwol, DIM, DIM);
    split_rows<<<(SQ * DIM) / 256, 256>>>(x, pxhi, pxlo);

    gemm_qkv<<<dim3(24, SQ / 128), 256, QKV_SMEM>>>(
        pxhi, pxlo, pwqh, pwql, pwkh, pwkl, pwvh, pwvl,
        pqh, pql, pkh, pkl, pvh, pvl, fc, fs);

    flash_mma<<<dim3(SQ / 128, NH), 256, FLASH_SMEM>>>(pqh, pql, pkh, pkl, pvh, pvl,
                                                       pahi, palo);

    gemm_out<<<dim3(DIM / 256, SQ / 128), 256, QKV_SMEM>>>(pahi, palo, pwoh, pwol, out);
}